// round 1
// baseline (speedup 1.0000x reference)
#include <cuda_runtime.h>
#include <math.h>

#define DIMC 384
#define NH 6
#define HD 64
#define BATCH 4
#define SEQ 4096
#define ATT_SCALE 0.125f
#define SM_STRIDE 68

// Scratch (allocation-free rule: device globals)
__device__ float g_qkv[(size_t)BATCH * SEQ * 3 * DIMC];   // [B*N, 3C]  (75.5 MB)
__device__ float g_attn[(size_t)BATCH * SEQ * DIMC];      // [B*N, C]   (25.2 MB)

// ---------------------------------------------------------------------------
// Generic 64x64-tile fp32 GEMM: C[M,N] = A[M,K] @ B[K,N] (+bias)
// 256 threads, 16x16 grid, 4x4 register microtile, BK=16.
// ---------------------------------------------------------------------------
template<bool HAS_BIAS>
__global__ __launch_bounds__(256) void gemm64(const float* __restrict__ A,
                                              const float* __restrict__ Bm,
                                              const float* __restrict__ bias,
                                              float* __restrict__ C,
                                              int M, int N, int K) {
    __shared__ float As[16][64];   // transposed: As[k][m]
    __shared__ float Bs[16][64];   // natural:    Bs[k][n]
    const int tid = threadIdx.x;
    const int tx = tid & 15, ty = tid >> 4;
    const int n0 = blockIdx.x << 6, m0 = blockIdx.y << 6;
    const int arow = tid >> 2, acol = (tid & 3) << 2;   // A: 4 thr/row, float4
    const int brow = tid >> 4, bcol = (tid & 15) << 2;  // B: 16 thr/row, float4
    float acc[4][4] = {};
    const float* Aptr = A + (size_t)(m0 + arow) * K + acol;
    const float* Bptr = Bm + (size_t)brow * N + n0 + bcol;

    for (int k0 = 0; k0 < K; k0 += 16) {
        float4 av = *(const float4*)(Aptr + k0);
        float4 bv = *(const float4*)(Bptr + (size_t)k0 * N);
        As[acol + 0][arow] = av.x;
        As[acol + 1][arow] = av.y;
        As[acol + 2][arow] = av.z;
        As[acol + 3][arow] = av.w;
        *(float4*)&Bs[brow][bcol] = bv;
        __syncthreads();
        #pragma unroll
        for (int kk = 0; kk < 16; kk++) {
            float4 a = *(float4*)&As[kk][ty << 2];
            float4 b = *(float4*)&Bs[kk][tx << 2];
            float aa[4] = {a.x, a.y, a.z, a.w};
            float bb[4] = {b.x, b.y, b.z, b.w};
            #pragma unroll
            for (int r = 0; r < 4; r++)
                #pragma unroll
                for (int c = 0; c < 4; c++)
                    acc[r][c] = fmaf(aa[r], bb[c], acc[r][c]);
        }
        __syncthreads();
    }

    #pragma unroll
    for (int r = 0; r < 4; r++) {
        float4 o;
        float* po = &o.x;
        #pragma unroll
        for (int c = 0; c < 4; c++) {
            float v = acc[r][c];
            if (HAS_BIAS) v += bias[n0 + (tx << 2) + c];
            po[c] = v;
        }
        *(float4*)&C[(size_t)(m0 + (ty << 2) + r) * N + n0 + (tx << 2)] = o;
    }
}

// ---------------------------------------------------------------------------
// Flash-style attention over qkv scratch.
// Grid: (SEQ/64, NH, BATCH). 256 threads (16x16), 4x4 microtiles.
// Per (b,h): Q,K,V rows live in g_qkv with row stride 3*DIMC.
// ---------------------------------------------------------------------------
__global__ __launch_bounds__(256) void attn64(const float* __restrict__ qkv,
                                              float* __restrict__ outp) {
    extern __shared__ float sm[];
    float* Qs = sm;                       // [d][qrow]  stride SM_STRIDE
    float* Ks = sm + 64 * SM_STRIDE;      // [d][kcol]  stride SM_STRIDE
    float* Vs = sm + 2 * 64 * SM_STRIDE;  // [krow][d]  stride SM_STRIDE
    float* Ps = sm + 3 * 64 * SM_STRIDE;  // [qrow][kcol]
    const int tid = threadIdx.x;
    const int tx = tid & 15, ty = tid >> 4;
    const int q0 = blockIdx.x << 6;
    const int h = blockIdx.y, b = blockIdx.z;
    const float* qb = qkv + ((size_t)b * SEQ) * (3 * DIMC) + h * HD;
    const float* kb = qb + DIMC;
    const float* vb = qb + 2 * DIMC;
    const int lrow = tid >> 4;            // 0..15
    const int d0 = (tid & 15) << 2;       // 0..60

    // Load Q tile transposed: Qs[d][row]
    #pragma unroll
    for (int rr = 0; rr < 4; rr++) {
        int r = lrow + rr * 16;
        float4 v = *(const float4*)&qb[(size_t)(q0 + r) * (3 * DIMC) + d0];
        Qs[(d0 + 0) * SM_STRIDE + r] = v.x;
        Qs[(d0 + 1) * SM_STRIDE + r] = v.y;
        Qs[(d0 + 2) * SM_STRIDE + r] = v.z;
        Qs[(d0 + 3) * SM_STRIDE + r] = v.w;
    }

    float m_i[4], l_i[4], acc[4][4];
    #pragma unroll
    for (int r = 0; r < 4; r++) {
        m_i[r] = -1e30f;
        l_i[r] = 0.f;
        #pragma unroll
        for (int c = 0; c < 4; c++) acc[r][c] = 0.f;
    }

    for (int t0 = 0; t0 < SEQ; t0 += 64) {
        __syncthreads();  // previous tile's Ps/Vs reads complete
        // Load K transposed + V natural
        #pragma unroll
        for (int rr = 0; rr < 4; rr++) {
            int r = lrow + rr * 16;
            float4 kv = *(const float4*)&kb[(size_t)(t0 + r) * (3 * DIMC) + d0];
            Ks[(d0 + 0) * SM_STRIDE + r] = kv.x;
            Ks[(d0 + 1) * SM_STRIDE + r] = kv.y;
            Ks[(d0 + 2) * SM_STRIDE + r] = kv.z;
            Ks[(d0 + 3) * SM_STRIDE + r] = kv.w;
            float4 vv = *(const float4*)&vb[(size_t)(t0 + r) * (3 * DIMC) + d0];
            *(float4*)&Vs[r * SM_STRIDE + d0] = vv;
        }
        __syncthreads();

        // S = Q @ K^T (4x4 per thread)
        float s[4][4] = {};
        #pragma unroll 16
        for (int d = 0; d < 64; d++) {
            float4 a = *(float4*)&Qs[d * SM_STRIDE + (ty << 2)];
            float4 bq = *(float4*)&Ks[d * SM_STRIDE + (tx << 2)];
            float aa[4] = {a.x, a.y, a.z, a.w};
            float bb[4] = {bq.x, bq.y, bq.z, bq.w};
            #pragma unroll
            for (int r = 0; r < 4; r++)
                #pragma unroll
                for (int c = 0; c < 4; c++)
                    s[r][c] = fmaf(aa[r], bb[c], s[r][c]);
        }

        // Online softmax (row groups = 16 lanes = one half-warp)
        #pragma unroll
        for (int r = 0; r < 4; r++) {
            #pragma unroll
            for (int c = 0; c < 4; c++) s[r][c] *= ATT_SCALE;
            float mx = fmaxf(fmaxf(s[r][0], s[r][1]), fmaxf(s[r][2], s[r][3]));
            #pragma unroll
            for (int off = 8; off >= 1; off >>= 1)
                mx = fmaxf(mx, __shfl_xor_sync(0xffffffffu, mx, off));
            float m_new = fmaxf(m_i[r], mx);
            float alpha = __expf(m_i[r] - m_new);
            float rs = 0.f;
            #pragma unroll
            for (int c = 0; c < 4; c++) {
                float p = __expf(s[r][c] - m_new);
                s[r][c] = p;
                rs += p;
            }
            #pragma unroll
            for (int off = 8; off >= 1; off >>= 1)
                rs += __shfl_xor_sync(0xffffffffu, rs, off);
            m_i[r] = m_new;
            l_i[r] = l_i[r] * alpha + rs;
            #pragma unroll
            for (int c = 0; c < 4; c++) acc[r][c] *= alpha;
            *(float4*)&Ps[((ty << 2) + r) * SM_STRIDE + (tx << 2)] =
                make_float4(s[r][0], s[r][1], s[r][2], s[r][3]);
        }
        __syncthreads();

        // O += P @ V
        #pragma unroll 16
        for (int j = 0; j < 64; j++) {
            float4 vv = *(float4*)&Vs[j * SM_STRIDE + (tx << 2)];
            float vvv[4] = {vv.x, vv.y, vv.z, vv.w};
            #pragma unroll
            for (int r = 0; r < 4; r++) {
                float p = Ps[((ty << 2) + r) * SM_STRIDE + j];
                #pragma unroll
                for (int c = 0; c < 4; c++)
                    acc[r][c] = fmaf(p, vvv[c], acc[r][c]);
            }
        }
    }

    // Epilogue: normalize and write [B*N, C] with column offset h*HD
    #pragma unroll
    for (int r = 0; r < 4; r++) {
        float inv = 1.0f / l_i[r];
        float4 o = make_float4(acc[r][0] * inv, acc[r][1] * inv,
                               acc[r][2] * inv, acc[r][3] * inv);
        *(float4*)&outp[((size_t)b * SEQ + q0 + (ty << 2) + r) * DIMC +
                        h * HD + (tx << 2)] = o;
    }
}

// ---------------------------------------------------------------------------
extern "C" void kernel_launch(void* const* d_in, const int* in_sizes, int n_in,
                              void* d_out, int out_size) {
    const float* x      = (const float*)d_in[0];
    const float* w_qkv  = (const float*)d_in[1];
    const float* w_proj = (const float*)d_in[2];
    const float* b_proj = (const float*)d_in[3];
    float* out = (float*)d_out;

    float *qkv_p, *attn_p;
    cudaGetSymbolAddress((void**)&qkv_p, g_qkv);
    cudaGetSymbolAddress((void**)&attn_p, g_attn);

    dim3 blk(256);

    // 1) qkv = x @ w_qkv   [16384, 1152]
    dim3 g1((3 * DIMC) / 64, (BATCH * SEQ) / 64);
    gemm64<false><<<g1, blk>>>(x, w_qkv, nullptr, qkv_p,
                               BATCH * SEQ, 3 * DIMC, DIMC);

    // 2) flash attention -> g_attn [16384, 384]
    const size_t attn_smem = 4 * 64 * SM_STRIDE * sizeof(float);  // 69632 B
    cudaFuncSetAttribute(attn64, cudaFuncAttributeMaxDynamicSharedMemorySize,
                         (int)attn_smem);
    dim3 g2(SEQ / 64, NH, BATCH);
    attn64<<<g2, blk, attn_smem>>>(qkv_p, attn_p);

    // 3) out = g_attn @ w_proj + b_proj   [16384, 384]
    dim3 g3(DIMC / 64, (BATCH * SEQ) / 64);
    gemm64<true><<<g3, blk>>>(attn_p, w_proj, b_proj, out,
                              BATCH * SEQ, DIMC, DIMC);
}